// round 1
// baseline (speedup 1.0000x reference)
#include <cuda_runtime.h>
#include <math.h>

// Problem constants
#define BMT 32      // B*M
#define NN 1024     // nodes
#define DD 128      // input dim
#define PP 64       // projection dim
#define NC 10       // clusters
#define FF 128      // output features
#define KK 10       // k neighbors
#define INV_SQRT11 0.30151134457776363f

// ---------------- scratch (device globals: allocation-free) ----------------
__device__ float g_Z[BMT * NN * PP];        // projected points
__device__ float g_sq[BMT * NN];            // squared norms
__device__ int   g_idx[BMT * NN * KK];      // knn indices
__device__ float g_Hc[BMT * NN * NC];       // cluster softmax probs
__device__ float g_Xs[BMT * NN * FF];       // X_trans * 1/sqrt(11)
__device__ int   g_cnt[BMT * NN];           // per-edge (column) degree of H_knn
__device__ int   g_start[BMT * NN];         // CSR starts
__device__ int   g_fill[BMT * NN];          // CSR fill cursors
__device__ int   g_list[BMT * NN * KK];     // CSR column lists (rows per edge)
__device__ float g_tmpE[BMT * NN * FF];     // De_inv * (H_knn^T @ Xs)
__device__ float g_tmpC[BMT * NC * FF];     // H_cluster^T @ Xs (unscaled)
__device__ float g_DeC[BMT * NC];           // cluster edge degrees

// ---------------- f32x2 helpers ----------------
__device__ __forceinline__ void fma2(unsigned long long& d,
                                     unsigned long long a,
                                     unsigned long long b) {
    asm("fma.rn.f32x2 %0, %1, %2, %3;" : "=l"(d) : "l"(a), "l"(b), "l"(d));
}
__device__ __forceinline__ unsigned long long add2(unsigned long long a,
                                                   unsigned long long b) {
    unsigned long long d;
    asm("add.rn.f32x2 %0, %1, %2;" : "=l"(d) : "l"(a), "l"(b));
    return d;
}

// ---------------- K0: zero accumulators ----------------
__global__ void k0_zero() {
    int t = blockIdx.x * blockDim.x + threadIdx.x;
    int stride = gridDim.x * blockDim.x;
    for (int i = t; i < BMT * NN; i += stride) g_cnt[i] = 0;
    for (int i = t; i < BMT * NC; i += stride) g_DeC[i] = 0.f;
    for (int i = t; i < BMT * NC * FF; i += stride) g_tmpC[i] = 0.f;
}

// ---------------- K1/K4: GEMM  out[bm,n,c] = (sum_d xflat[bm,n,d]*W[c,d] + bias[c]) * scale
// MODE 0: -> g_Z (NCOLS=64)   MODE 1: -> g_Xs (NCOLS=128)
template <int MODE>
__global__ void __launch_bounds__(256) k_gemm(const float* __restrict__ X,
                                              const float* __restrict__ W,
                                              const float* __restrict__ bias,
                                              float scale) {
    constexpr int NCOLS = (MODE == 0) ? PP : FF;
    float* outp = (MODE == 0) ? g_Z : g_Xs;
    __shared__ float sA[64][33];
    __shared__ float sW[64][33];
    int bm = blockIdx.x;
    int row0 = blockIdx.y * 64;
    int col0 = blockIdx.z * 64;
    int b = bm >> 3, m = bm & 7;
    int tid = threadIdx.x;
    int tr = tid >> 4, tc = tid & 15;
    float acc[4][4] = {};
    // xflat[bm, n, d] = x[((b*NN + n)*8 + m)*DD + d]; row stride = 1024 floats
    const float* xbase = X + ((size_t)(b * NN) * 8 + m) * DD;
    for (int k0 = 0; k0 < DD; k0 += 32) {
        for (int t = tid; t < 64 * 32; t += 256) {
            int r = t >> 5, k = t & 31;
            sA[r][k] = xbase[(size_t)(row0 + r) * 1024 + k0 + k];
            sW[r][k] = W[(col0 + r) * DD + k0 + k];
        }
        __syncthreads();
#pragma unroll
        for (int k = 0; k < 32; k++) {
            float a[4], w[4];
#pragma unroll
            for (int i = 0; i < 4; i++) a[i] = sA[tr * 4 + i][k];
#pragma unroll
            for (int j = 0; j < 4; j++) w[j] = sW[tc * 4 + j][k];
#pragma unroll
            for (int i = 0; i < 4; i++)
#pragma unroll
                for (int j = 0; j < 4; j++)
                    acc[i][j] = fmaf(a[i], w[j], acc[i][j]);
        }
        __syncthreads();
    }
#pragma unroll
    for (int i = 0; i < 4; i++) {
        int n = row0 + tr * 4 + i;
#pragma unroll
        for (int j = 0; j < 4; j++) {
            int c = col0 + tc * 4 + j;
            outp[((size_t)bm * NN + n) * NCOLS + c] = (acc[i][j] + bias[c]) * scale;
        }
    }
}

// ---------------- K1b: squared norms (warp per row) ----------------
__global__ void k_sq() {
    int row = (blockIdx.x * blockDim.x + threadIdx.x) >> 5;
    int lane = threadIdx.x & 31;
    if (row >= BMT * NN) return;
    const float* z = g_Z + (size_t)row * PP;
    float a = z[lane], b = z[lane + 32];
    float v = a * a + b * b;
#pragma unroll
    for (int o = 16; o; o >>= 1) v += __shfl_xor_sync(0xffffffffu, v, o);
    if (lane == 0) g_sq[row] = v;
}

// ---------------- K2: Gram + streaming top-10 smallest d2 ----------------
__global__ void __launch_bounds__(128) k_knn() {
    int bm = blockIdx.y;
    int n = blockIdx.x * 128 + threadIdx.x;
    const float* Zb = g_Z + (size_t)bm * NN * PP;

    // own row packed as f32x2 pairs
    unsigned long long zp[32];
    const unsigned long long* zr =
        (const unsigned long long*)(Zb + (size_t)n * PP);
#pragma unroll
    for (int i = 0; i < 32; i++) zp[i] = zr[i];
    float sqi = g_sq[bm * NN + n];

    float vals[KK];
    int idxs[KK];
#pragma unroll
    for (int k = 0; k < KK; k++) {
        vals[k] = __int_as_float(0x7f800000);  // +inf
        idxs[k] = 0;
    }

    __shared__ __align__(16) float sZ[32 * 64];
    __shared__ float ssq[32];

    for (int j0 = 0; j0 < NN; j0 += 32) {
        __syncthreads();
#pragma unroll
        for (int t = threadIdx.x; t < 2048; t += 128)
            sZ[t] = Zb[(size_t)j0 * 64 + t];
        if (threadIdx.x < 32) ssq[threadIdx.x] = g_sq[bm * NN + j0 + threadIdx.x];
        __syncthreads();

#pragma unroll 1
        for (int j = 0; j < 32; j++) {
            const ulonglong2* c2 = (const ulonglong2*)(sZ + j * 64);
            unsigned long long a0 = 0ull, a1 = 0ull, a2 = 0ull, a3 = 0ull;
#pragma unroll
            for (int i = 0; i < 8; i++) {
                ulonglong2 v0 = c2[2 * i];
                fma2(a0, zp[4 * i + 0], v0.x);
                fma2(a1, zp[4 * i + 1], v0.y);
                ulonglong2 v1 = c2[2 * i + 1];
                fma2(a2, zp[4 * i + 2], v1.x);
                fma2(a3, zp[4 * i + 3], v1.y);
            }
            a0 = add2(a0, a1);
            a2 = add2(a2, a3);
            a0 = add2(a0, a2);
            float lo = __uint_as_float((unsigned)(a0 & 0xffffffffull));
            float hi = __uint_as_float((unsigned)(a0 >> 32));
            float dot = lo + hi;
            float d2 = sqi + ssq[j] - 2.f * dot;
            if (d2 < vals[KK - 1]) {
                vals[KK - 1] = d2;
                idxs[KK - 1] = j0 + j;
#pragma unroll
                for (int p = KK - 1; p > 0; --p) {
                    bool s = vals[p] < vals[p - 1];  // strict: lower index wins ties
                    float va = vals[p - 1];
                    int ia = idxs[p - 1];
                    vals[p - 1] = s ? vals[p] : va;
                    idxs[p - 1] = s ? idxs[p] : ia;
                    vals[p] = s ? va : vals[p];
                    idxs[p] = s ? ia : idxs[p];
                }
            }
        }
    }

    int base = (bm * NN + n) * KK;
#pragma unroll
    for (int k = 0; k < KK; k++) {
        g_idx[base + k] = idxs[k];
        atomicAdd(&g_cnt[bm * NN + idxs[k]], 1);
    }
}

// ---------------- K3: cluster softmax + DeC (warp per row) ----------------
__global__ void __launch_bounds__(256) k_cluster(const float* __restrict__ C) {
    __shared__ float sDeC[NC];
    if (threadIdx.x < NC) sDeC[threadIdx.x] = 0.f;
    __syncthreads();
    int warp = threadIdx.x >> 5;
    int lane = threadIdx.x & 31;
    int row = blockIdx.x * 8 + warp;  // 8 rows per block, same bm (8 | 1024)
    int bm = row >> 10;
    const float* z = g_Z + (size_t)row * PP;
    float z0 = z[lane], z1 = z[lane + 32];
    float lg[NC];
#pragma unroll
    for (int c = 0; c < NC; c++)
        lg[c] = fmaf(z1, C[c * PP + 32 + lane], z0 * C[c * PP + lane]);
#pragma unroll
    for (int c = 0; c < NC; c++)
#pragma unroll
        for (int o = 16; o; o >>= 1)
            lg[c] += __shfl_xor_sync(0xffffffffu, lg[c], o);
    if (lane == 0) {
        float mx = lg[0];
#pragma unroll
        for (int c = 1; c < NC; c++) mx = fmaxf(mx, lg[c]);
        float e[NC], sum = 0.f;
#pragma unroll
        for (int c = 0; c < NC; c++) {
            e[c] = expf(lg[c] - mx);
            sum += e[c];
        }
        float inv = 1.f / sum;
#pragma unroll
        for (int c = 0; c < NC; c++) {
            float pv = e[c] * inv;
            g_Hc[(size_t)row * NC + c] = pv;
            atomicAdd(&sDeC[c], pv);
        }
    }
    __syncthreads();
    if (threadIdx.x < NC) atomicAdd(&g_DeC[bm * NC + threadIdx.x], sDeC[threadIdx.x]);
}

// ---------------- K5a: per-bm exclusive scan of counts ----------------
__global__ void __launch_bounds__(1024) k_scan() {
    int bm = blockIdx.x;
    __shared__ int s[NN];
    int t = threadIdx.x;
    int v = g_cnt[bm * NN + t];
    s[t] = v;
    __syncthreads();
    for (int off = 1; off < NN; off <<= 1) {
        int add = (t >= off) ? s[t - off] : 0;
        __syncthreads();
        s[t] += add;
        __syncthreads();
    }
    int excl = s[t] - v;
    g_start[bm * NN + t] = excl;
    g_fill[bm * NN + t] = excl;
}

// ---------------- K5b: fill CSR column lists ----------------
__global__ void k_fill() {
    int gid = blockIdx.x * blockDim.x + threadIdx.x;  // row id 0..32767
    if (gid >= BMT * NN) return;
    int bm = gid >> 10;
    int n = gid & (NN - 1);
#pragma unroll
    for (int k = 0; k < KK; k++) {
        int j = g_idx[gid * KK + k];
        int pos = atomicAdd(&g_fill[bm * NN + j], 1);
        g_list[(size_t)bm * NN * KK + pos] = n;
    }
}

// ---------------- K6: edge aggregation  tmpE[bm,j,:] = De_inv * sum Xs[rows] ----------------
__global__ void __launch_bounds__(128) k_edge() {
    int j = blockIdx.x;
    int bm = blockIdx.y;
    int f = threadIdx.x;
    int cnt = g_cnt[bm * NN + j];
    int st = g_start[bm * NN + j];
    const int* lst = g_list + (size_t)bm * NN * KK + st;
    float acc = 0.f;
    for (int i = 0; i < cnt; i++) {
        int n = lst[i];
        acc += g_Xs[((size_t)bm * NN + n) * FF + f];
    }
    float sc = (cnt > 0) ? (1.f / (float)cnt) : 0.f;
    g_tmpE[((size_t)bm * NN + j) * FF + f] = acc * sc;
}

// ---------------- K6b: cluster aggregation  tmpC[bm,c,:] += sum Hc[n,c]*Xs[n,:] ----------------
__global__ void __launch_bounds__(128) k_cagg() {
    int bm = blockIdx.y;
    int base = blockIdx.x * 128;  // 8 chunks of 128 rows
    int f = threadIdx.x;
    __shared__ float sH[128 * NC];
    for (int t = f; t < 128 * NC; t += 128)
        sH[t] = g_Hc[((size_t)bm * NN + base) * NC + t];
    __syncthreads();
    float acc[NC] = {};
    for (int nn = 0; nn < 128; nn++) {
        float x = g_Xs[((size_t)bm * NN + base + nn) * FF + f];
#pragma unroll
        for (int c = 0; c < NC; c++) acc[c] = fmaf(sH[nn * NC + c], x, acc[c]);
    }
#pragma unroll
    for (int c = 0; c < NC; c++)
        atomicAdd(&g_tmpC[((size_t)bm * NC + c) * FF + f], acc[c]);
}

// ---------------- K7: final gather + cluster term + elu + output layout ----------------
__global__ void __launch_bounds__(128) k_final(float* __restrict__ out) {
    int bm = blockIdx.y;
    int base = blockIdx.x * 32;
    int f = threadIdx.x;
    __shared__ float sC[NC * FF];
    __shared__ float sH[32 * NC];
    __shared__ int sI[32 * KK];
    __shared__ float sDi[NC];
    if (f < NC) sDi[f] = 1.f / g_DeC[bm * NC + f];
    __syncthreads();
#pragma unroll
    for (int c = 0; c < NC; c++)
        sC[c * FF + f] = g_tmpC[((size_t)bm * NC + c) * FF + f] * sDi[c];
    for (int t = f; t < 32 * NC; t += 128) {
        sH[t] = g_Hc[((size_t)bm * NN + base) * NC + t];
        sI[t] = g_idx[((size_t)bm * NN + base) * KK + t];
    }
    __syncthreads();
    int b = bm >> 3, m = bm & 7;
    for (int r = 0; r < 32; r++) {
        float acc = 0.f;
#pragma unroll
        for (int k = 0; k < KK; k++) {
            int j = sI[r * KK + k];
            acc += g_tmpE[((size_t)bm * NN + j) * FF + f];
        }
#pragma unroll
        for (int c = 0; c < NC; c++)
            acc = fmaf(sH[r * NC + c], sC[c * FF + f], acc);
        float v = INV_SQRT11 * acc;
        v = (v > 0.f) ? v : expm1f(v);
        out[(((size_t)b * NN + base + r) * 8 + m) * FF + f] = v;
    }
}

// ---------------- launch ----------------
extern "C" void kernel_launch(void* const* d_in, const int* in_sizes, int n_in,
                              void* d_out, int out_size) {
    const float* x   = (const float*)d_in[0];  // [4,1024,8,128]
    const float* Wp  = (const float*)d_in[1];  // [64,128]
    const float* Wpb = (const float*)d_in[2];  // [64]
    const float* C   = (const float*)d_in[3];  // [10,64]
    const float* Tw  = (const float*)d_in[4];  // [128,128]
    const float* Tb  = (const float*)d_in[5];  // [128]
    float* out = (float*)d_out;

    k0_zero<<<64, 256>>>();
    k_gemm<0><<<dim3(BMT, NN / 64, PP / 64), 256>>>(x, Wp, Wpb, 1.0f);   // Z
    k_sq<<<(BMT * NN * 32) / 256, 256>>>();                               // sq
    k_cluster<<<(BMT * NN) / 8, 256>>>(C);                                // softmax + DeC
    k_knn<<<dim3(NN / 128, BMT), 128>>>();                                // Gram + top-10
    k_gemm<1><<<dim3(BMT, NN / 64, FF / 64), 256>>>(x, Tw, Tb, INV_SQRT11); // Xs
    k_scan<<<BMT, 1024>>>();                                              // CSR starts
    k_fill<<<(BMT * NN + 255) / 256, 256>>>();                            // CSR lists
    k_edge<<<dim3(NN, BMT), 128>>>();                                     // H_knn^T @ Xs (+De_inv)
    k_cagg<<<dim3(NN / 128, BMT), 128>>>();                               // H_c^T @ Xs
    k_final<<<dim3(NN / 32, BMT), 128>>>(out);                            // H @ (...) + elu
}

// round 2
// speedup vs baseline: 1.0153x; 1.0153x over previous
#include <cuda_runtime.h>
#include <math.h>

typedef unsigned long long ull;

// Problem constants
#define BMT 32      // B*M
#define NN 1024     // nodes
#define DD 128      // input dim
#define PP 64       // projection dim
#define NC 10       // clusters
#define FF 128      // output features
#define KK 10       // k neighbors
#define INV_SQRT11 0.30151134457776363f

// ---------------- scratch (device globals: allocation-free) ----------------
__device__ float g_Z[BMT * NN * PP];        // projected points
__device__ float g_sq[BMT * NN];            // squared norms
__device__ int   g_idx[BMT * NN * KK];      // knn indices
__device__ float g_Hc[BMT * NN * NC];       // cluster softmax probs
__device__ float g_Xs[BMT * NN * FF];       // X_trans * 1/sqrt(11)
__device__ int   g_cnt[BMT * NN];           // per-edge (column) degree of H_knn
__device__ int   g_start[BMT * NN];         // CSR starts
__device__ int   g_fill[BMT * NN];          // CSR fill cursors
__device__ int   g_list[BMT * NN * KK];     // CSR column lists (rows per edge)
__device__ float g_tmpE[BMT * NN * FF];     // De_inv * (H_knn^T @ Xs)
__device__ float g_tmpC[BMT * NC * FF];     // H_cluster^T @ Xs (unscaled)
__device__ float g_DeC[BMT * NC];           // cluster edge degrees

// ---------------- f32x2 helpers ----------------
__device__ __forceinline__ void fma2(ull& d, ull a, ull b) {
    asm("fma.rn.f32x2 %0, %1, %2, %3;" : "=l"(d) : "l"(a), "l"(b), "l"(d));
}
__device__ __forceinline__ ull add2(ull a, ull b) {
    ull d;
    asm("add.rn.f32x2 %0, %1, %2;" : "=l"(d) : "l"(a), "l"(b));
    return d;
}
__device__ __forceinline__ ull dup2(float a) {
    ull d;
    unsigned r = __float_as_uint(a);
    asm("mov.b64 %0, {%1, %1};" : "=l"(d) : "r"(r));
    return d;
}
__device__ __forceinline__ void unpack2(ull v, float& lo, float& hi) {
    unsigned a, b;
    asm("mov.b64 {%0, %1}, %2;" : "=r"(a), "=r"(b) : "l"(v));
    lo = __uint_as_float(a);
    hi = __uint_as_float(b);
}

// ---------------- K0: zero accumulators ----------------
__global__ void k0_zero() {
    int t = blockIdx.x * blockDim.x + threadIdx.x;
    int stride = gridDim.x * blockDim.x;
    for (int i = t; i < BMT * NN; i += stride) g_cnt[i] = 0;
    for (int i = t; i < BMT * NC; i += stride) g_DeC[i] = 0.f;
    for (int i = t; i < BMT * NC * FF; i += stride) g_tmpC[i] = 0.f;
}

// ---------------- GEMM (f32x2 packed): out[bm,n,c] = (sum_d x*W + b) * scale
// MODE 0: -> g_Z (NCOLS=64)   MODE 1: -> g_Xs (NCOLS=128)
// Block: 128 threads. Tile: 64 rows x 64 cols. Thread tile: 4 rows x 8 cols.
template <int MODE>
__global__ void __launch_bounds__(128) k_gemm(const float* __restrict__ X,
                                              const float* __restrict__ W,
                                              const float* __restrict__ bias,
                                              float scale) {
    constexpr int NCOLS = (MODE == 0) ? PP : FF;
    float* outp = (MODE == 0) ? g_Z : g_Xs;
    __shared__ __align__(16) float sAT[32][72];  // [k][row]
    __shared__ __align__(16) float sWT[32][72];  // [k][col]
    int bm = blockIdx.x;
    int row0 = blockIdx.y * 64;
    int col0 = blockIdx.z * 64;
    int b = bm >> 3, m = bm & 7;
    int tid = threadIdx.x;
    int tr = tid >> 3;  // 0..15 -> 4 rows each
    int tc = tid & 7;   // 0..7  -> 8 cols each
    ull acc2[4][4] = {};
    // xflat[bm,n,d] = X[((b*NN+n)*8+m)*DD + d]; row stride 1024 floats
    const float* xbase = X + ((size_t)(b * NN) * 8 + m) * DD;
    for (int k0 = 0; k0 < DD; k0 += 32) {
        for (int t = tid; t < 64 * 32; t += 128) {
            int r = t >> 5, k = t & 31;
            sAT[k][r] = xbase[(size_t)(row0 + r) * 1024 + k0 + k];
            sWT[k][r] = W[(col0 + r) * DD + k0 + k];
        }
        __syncthreads();
#pragma unroll
        for (int k = 0; k < 32; k++) {
            float4 a4 = *(const float4*)&sAT[k][tr * 4];
            ulonglong2 wA = *(const ulonglong2*)&sWT[k][tc * 8];
            ulonglong2 wB = *(const ulonglong2*)&sWT[k][tc * 8 + 4];
            ull a0 = dup2(a4.x), a1 = dup2(a4.y), a2 = dup2(a4.z), a3 = dup2(a4.w);
            fma2(acc2[0][0], a0, wA.x); fma2(acc2[0][1], a0, wA.y);
            fma2(acc2[0][2], a0, wB.x); fma2(acc2[0][3], a0, wB.y);
            fma2(acc2[1][0], a1, wA.x); fma2(acc2[1][1], a1, wA.y);
            fma2(acc2[1][2], a1, wB.x); fma2(acc2[1][3], a1, wB.y);
            fma2(acc2[2][0], a2, wA.x); fma2(acc2[2][1], a2, wA.y);
            fma2(acc2[2][2], a2, wB.x); fma2(acc2[2][3], a2, wB.y);
            fma2(acc2[3][0], a3, wA.x); fma2(acc2[3][1], a3, wA.y);
            fma2(acc2[3][2], a3, wB.x); fma2(acc2[3][3], a3, wB.y);
        }
        __syncthreads();
    }
    // epilogue
    float bv[8];
#pragma unroll
    for (int j = 0; j < 8; j++) bv[j] = bias[col0 + tc * 8 + j];
#pragma unroll
    for (int i = 0; i < 4; i++) {
        int n = row0 + tr * 4 + i;
        float f[8];
#pragma unroll
        for (int j2 = 0; j2 < 4; j2++) unpack2(acc2[i][j2], f[2 * j2], f[2 * j2 + 1]);
        float4 o0, o1;
        o0.x = (f[0] + bv[0]) * scale; o0.y = (f[1] + bv[1]) * scale;
        o0.z = (f[2] + bv[2]) * scale; o0.w = (f[3] + bv[3]) * scale;
        o1.x = (f[4] + bv[4]) * scale; o1.y = (f[5] + bv[5]) * scale;
        o1.z = (f[6] + bv[6]) * scale; o1.w = (f[7] + bv[7]) * scale;
        float* op = outp + ((size_t)bm * NN + n) * NCOLS + col0 + tc * 8;
        *(float4*)op = o0;
        *(float4*)(op + 4) = o1;
    }
}

// ---------------- K_cluster_sq: thread-per-row cluster softmax + DeC + sq norm ----
__global__ void __launch_bounds__(256) k_cluster_sq(const float* __restrict__ C) {
    __shared__ float sC[NC * PP];
    __shared__ float sDeC[NC];
    int tid = threadIdx.x;
    for (int t = tid; t < NC * PP; t += 256) sC[t] = C[t];
    if (tid < NC) sDeC[tid] = 0.f;
    __syncthreads();
    int row = blockIdx.x * 256 + tid;
    int bm = row >> 10;
    const float4* z4 = (const float4*)(g_Z + (size_t)row * PP);
    float acc[NC] = {};
    float sq = 0.f;
#pragma unroll
    for (int i = 0; i < 16; i++) {
        float4 v = z4[i];
        sq = fmaf(v.x, v.x, fmaf(v.y, v.y, fmaf(v.z, v.z, fmaf(v.w, v.w, sq))));
#pragma unroll
        for (int c = 0; c < NC; c++) {
            const float* cp = &sC[c * PP + i * 4];
            acc[c] = fmaf(v.x, cp[0], acc[c]);
            acc[c] = fmaf(v.y, cp[1], acc[c]);
            acc[c] = fmaf(v.z, cp[2], acc[c]);
            acc[c] = fmaf(v.w, cp[3], acc[c]);
        }
    }
    g_sq[row] = sq;
    float mx = acc[0];
#pragma unroll
    for (int c = 1; c < NC; c++) mx = fmaxf(mx, acc[c]);
    float p[NC], sum = 0.f;
#pragma unroll
    for (int c = 0; c < NC; c++) {
        p[c] = expf(acc[c] - mx);
        sum += p[c];
    }
    float inv = 1.f / sum;
#pragma unroll
    for (int c = 0; c < NC; c++) {
        p[c] *= inv;
        g_Hc[(size_t)row * NC + c] = p[c];
    }
    // warp-reduce p[c] then one smem atomic per warp per c
#pragma unroll
    for (int c = 0; c < NC; c++)
#pragma unroll
        for (int o = 16; o; o >>= 1) p[c] += __shfl_xor_sync(0xffffffffu, p[c], o);
    if ((tid & 31) == 0) {
#pragma unroll
        for (int c = 0; c < NC; c++) atomicAdd(&sDeC[c], p[c]);
    }
    __syncthreads();
    if (tid < NC) atomicAdd(&g_DeC[bm * NC + tid], sDeC[tid]);
}

// ---------------- K2: Gram + streaming top-10 smallest d2 ----------------
__global__ void __launch_bounds__(128) k_knn() {
    int bm = blockIdx.y;
    int n = blockIdx.x * 128 + threadIdx.x;
    const float* Zb = g_Z + (size_t)bm * NN * PP;

    // own row packed as f32x2 pairs
    ull zp[32];
    const ull* zr = (const ull*)(Zb + (size_t)n * PP);
#pragma unroll
    for (int i = 0; i < 32; i++) zp[i] = zr[i];
    float sqi = g_sq[bm * NN + n];

    float vals[KK];
    int idxs[KK];
#pragma unroll
    for (int k = 0; k < KK; k++) {
        vals[k] = __int_as_float(0x7f800000);  // +inf
        idxs[k] = 0;
    }

    __shared__ __align__(16) float sZ[32 * 64];
    __shared__ float ssq[32];

    for (int j0 = 0; j0 < NN; j0 += 32) {
        __syncthreads();
#pragma unroll
        for (int t = threadIdx.x; t < 2048; t += 128)
            sZ[t] = Zb[(size_t)j0 * 64 + t];
        if (threadIdx.x < 32) ssq[threadIdx.x] = g_sq[bm * NN + j0 + threadIdx.x];
        __syncthreads();

#pragma unroll 2
        for (int j = 0; j < 32; j++) {
            const ulonglong2* c2 = (const ulonglong2*)(sZ + j * 64);
            ull a0 = 0ull, a1 = 0ull, a2 = 0ull, a3 = 0ull;
#pragma unroll
            for (int i = 0; i < 8; i++) {
                ulonglong2 v0 = c2[2 * i];
                fma2(a0, zp[4 * i + 0], v0.x);
                fma2(a1, zp[4 * i + 1], v0.y);
                ulonglong2 v1 = c2[2 * i + 1];
                fma2(a2, zp[4 * i + 2], v1.x);
                fma2(a3, zp[4 * i + 3], v1.y);
            }
            a0 = add2(a0, a1);
            a2 = add2(a2, a3);
            a0 = add2(a0, a2);
            float lo, hi;
            unpack2(a0, lo, hi);
            float dot = lo + hi;
            float d2 = sqi + ssq[j] - 2.f * dot;
            if (d2 < vals[KK - 1]) {
                vals[KK - 1] = d2;
                idxs[KK - 1] = j0 + j;
#pragma unroll
                for (int p = KK - 1; p > 0; --p) {
                    bool s = vals[p] < vals[p - 1];  // strict: lower index wins ties
                    float va = vals[p - 1];
                    int ia = idxs[p - 1];
                    vals[p - 1] = s ? vals[p] : va;
                    idxs[p - 1] = s ? idxs[p] : ia;
                    vals[p] = s ? va : vals[p];
                    idxs[p] = s ? ia : idxs[p];
                }
            }
        }
    }

    int base = (bm * NN + n) * KK;
#pragma unroll
    for (int k = 0; k < KK; k++) {
        g_idx[base + k] = idxs[k];
        atomicAdd(&g_cnt[bm * NN + idxs[k]], 1);
    }
}

// ---------------- K5a: per-bm exclusive scan of counts ----------------
__global__ void __launch_bounds__(1024) k_scan() {
    int bm = blockIdx.x;
    __shared__ int s[NN];
    int t = threadIdx.x;
    int v = g_cnt[bm * NN + t];
    s[t] = v;
    __syncthreads();
    for (int off = 1; off < NN; off <<= 1) {
        int add = (t >= off) ? s[t - off] : 0;
        __syncthreads();
        s[t] += add;
        __syncthreads();
    }
    int excl = s[t] - v;
    g_start[bm * NN + t] = excl;
    g_fill[bm * NN + t] = excl;
}

// ---------------- K5b: fill CSR column lists ----------------
__global__ void k_fill() {
    int gid = blockIdx.x * blockDim.x + threadIdx.x;  // row id 0..32767
    if (gid >= BMT * NN) return;
    int bm = gid >> 10;
    int n = gid & (NN - 1);
#pragma unroll
    for (int k = 0; k < KK; k++) {
        int j = g_idx[gid * KK + k];
        int pos = atomicAdd(&g_fill[bm * NN + j], 1);
        g_list[(size_t)bm * NN * KK + pos] = n;
    }
}

// ---------------- K6: edge aggregation  tmpE[bm,j,:] = De_inv * sum Xs[rows] ----------------
__global__ void __launch_bounds__(128) k_edge() {
    int j = blockIdx.x;
    int bm = blockIdx.y;
    int f = threadIdx.x;
    int cnt = g_cnt[bm * NN + j];
    int st = g_start[bm * NN + j];
    const int* lst = g_list + (size_t)bm * NN * KK + st;
    const float* Xb = g_Xs + (size_t)bm * NN * FF;
    float acc0 = 0.f, acc1 = 0.f, acc2v = 0.f, acc3 = 0.f;
    int i = 0;
    for (; i + 4 <= cnt; i += 4) {
        int n0 = lst[i], n1 = lst[i + 1], n2 = lst[i + 2], n3 = lst[i + 3];
        float v0 = Xb[(size_t)n0 * FF + f];
        float v1 = Xb[(size_t)n1 * FF + f];
        float v2 = Xb[(size_t)n2 * FF + f];
        float v3 = Xb[(size_t)n3 * FF + f];
        acc0 += v0; acc1 += v1; acc2v += v2; acc3 += v3;
    }
    for (; i < cnt; i++) acc0 += Xb[(size_t)lst[i] * FF + f];
    float acc = (acc0 + acc1) + (acc2v + acc3);
    float sc = (cnt > 0) ? (1.f / (float)cnt) : 0.f;
    g_tmpE[((size_t)bm * NN + j) * FF + f] = acc * sc;
}

// ---------------- K6b: cluster aggregation  tmpC[bm,c,:] += sum Hc[n,c]*Xs[n,:] ----------------
__global__ void __launch_bounds__(128) k_cagg() {
    int bm = blockIdx.y;
    int base = blockIdx.x * 128;  // 8 chunks of 128 rows
    int f = threadIdx.x;
    __shared__ float sH[128 * NC];
    for (int t = f; t < 128 * NC; t += 128)
        sH[t] = g_Hc[((size_t)bm * NN + base) * NC + t];
    __syncthreads();
    float acc[NC] = {};
#pragma unroll 4
    for (int nn = 0; nn < 128; nn++) {
        float x = g_Xs[((size_t)bm * NN + base + nn) * FF + f];
#pragma unroll
        for (int c = 0; c < NC; c++) acc[c] = fmaf(sH[nn * NC + c], x, acc[c]);
    }
#pragma unroll
    for (int c = 0; c < NC; c++)
        atomicAdd(&g_tmpC[((size_t)bm * NC + c) * FF + f], acc[c]);
}

// ---------------- K7: final gather + cluster term + elu + output layout ----------------
__global__ void __launch_bounds__(128) k_final(float* __restrict__ out) {
    int bm = blockIdx.y;
    int base = blockIdx.x * 32;
    int f = threadIdx.x;
    __shared__ float sC[NC * FF];
    __shared__ float sH[32 * NC];
    __shared__ int sI[32 * KK];
    __shared__ float sDi[NC];
    if (f < NC) sDi[f] = 1.f / g_DeC[bm * NC + f];
    __syncthreads();
#pragma unroll
    for (int c = 0; c < NC; c++)
        sC[c * FF + f] = g_tmpC[((size_t)bm * NC + c) * FF + f] * sDi[c];
    for (int t = f; t < 32 * NC; t += 128) {
        sH[t] = g_Hc[((size_t)bm * NN + base) * NC + t];
        sI[t] = g_idx[((size_t)bm * NN + base) * KK + t];
    }
    __syncthreads();
    int b = bm >> 3, m = bm & 7;
    const float* Eb = g_tmpE + (size_t)bm * NN * FF;
#pragma unroll 2
    for (int r = 0; r < 32; r++) {
        float acc = 0.f;
#pragma unroll
        for (int k = 0; k < KK; k++) {
            int j = sI[r * KK + k];
            acc += Eb[(size_t)j * FF + f];
        }
#pragma unroll
        for (int c = 0; c < NC; c++)
            acc = fmaf(sH[r * NC + c], sC[c * FF + f], acc);
        float v = INV_SQRT11 * acc;
        v = (v > 0.f) ? v : expm1f(v);
        out[(((size_t)b * NN + base + r) * 8 + m) * FF + f] = v;
    }
}

// ---------------- launch ----------------
extern "C" void kernel_launch(void* const* d_in, const int* in_sizes, int n_in,
                              void* d_out, int out_size) {
    const float* x   = (const float*)d_in[0];  // [4,1024,8,128]
    const float* Wp  = (const float*)d_in[1];  // [64,128]
    const float* Wpb = (const float*)d_in[2];  // [64]
    const float* C   = (const float*)d_in[3];  // [10,64]
    const float* Tw  = (const float*)d_in[4];  // [128,128]
    const float* Tb  = (const float*)d_in[5];  // [128]
    float* out = (float*)d_out;

    k0_zero<<<64, 256>>>();                                                  // 1
    k_gemm<0><<<dim3(BMT, NN / 64, 1), 128>>>(x, Wp, Wpb, 1.0f);             // 2: Z
    k_cluster_sq<<<(BMT * NN) / 256, 256>>>(C);                              // 3: softmax+DeC+sq
    k_knn<<<dim3(NN / 128, BMT), 128>>>();                                   // 4: Gram + top-10
    k_gemm<1><<<dim3(BMT, NN / 64, 2), 128>>>(x, Tw, Tb, INV_SQRT11);        // 5: Xs
    k_scan<<<BMT, 1024>>>();                                                 // 6
    k_fill<<<(BMT * NN + 255) / 256, 256>>>();                               // 7
    k_edge<<<dim3(NN, BMT), 128>>>();                                        // 8
    k_cagg<<<dim3(NN / 128, BMT), 128>>>();                                  // 9
    k_final<<<dim3(NN / 32, BMT), 128>>>(out);                               // 10
}

// round 3
// speedup vs baseline: 1.0301x; 1.0146x over previous
#include <cuda_runtime.h>
#include <math.h>

typedef unsigned long long ull;

// Problem constants
#define BMT 32      // B*M
#define NN 1024     // nodes
#define DD 128      // input dim
#define PP 64       // projection dim
#define NC 10       // clusters
#define FF 128      // output features
#define KK 10       // k neighbors
#define NSPLIT 4    // kNN candidate-dimension splits
#define JCHUNK (NN / NSPLIT)
#define INV_SQRT11 0.30151134457776363f

// ---------------- scratch (device globals: allocation-free) ----------------
__device__ float g_Z[BMT * NN * PP];        // projected points
__device__ float g_sq[BMT * NN];            // squared norms
__device__ int   g_idx[BMT * NN * KK];      // knn indices
__device__ float g_Hc[BMT * NN * NC];       // cluster softmax probs
__device__ float g_Xs[BMT * NN * FF];       // X_trans * 1/sqrt(11)
__device__ int   g_cnt[BMT * NN];           // per-edge (column) degree of H_knn
__device__ int   g_start[BMT * NN];         // CSR starts
__device__ int   g_fill[BMT * NN];          // CSR fill cursors
__device__ int   g_list[BMT * NN * KK];     // CSR column lists (rows per edge)
__device__ float g_tmpE[BMT * NN * FF];     // De_inv * (H_knn^T @ Xs)
__device__ float g_tmpC[BMT * NC * FF];     // H_cluster^T @ Xs (unscaled)
__device__ float g_DeC[BMT * NC];           // cluster edge degrees
__device__ float g_pval[BMT * NN * NSPLIT * KK];  // partial top-10 values
__device__ int   g_pidx[BMT * NN * NSPLIT * KK];  // partial top-10 indices

// ---------------- f32x2 helpers ----------------
__device__ __forceinline__ void fma2(ull& d, ull a, ull b) {
    asm("fma.rn.f32x2 %0, %1, %2, %3;" : "=l"(d) : "l"(a), "l"(b), "l"(d));
}
__device__ __forceinline__ ull add2(ull a, ull b) {
    ull d;
    asm("add.rn.f32x2 %0, %1, %2;" : "=l"(d) : "l"(a), "l"(b));
    return d;
}
__device__ __forceinline__ ull dup2(float a) {
    ull d;
    unsigned r = __float_as_uint(a);
    asm("mov.b64 %0, {%1, %1};" : "=l"(d) : "r"(r));
    return d;
}
__device__ __forceinline__ void unpack2(ull v, float& lo, float& hi) {
    unsigned a, b;
    asm("mov.b64 {%0, %1}, %2;" : "=r"(a), "=r"(b) : "l"(v));
    lo = __uint_as_float(a);
    hi = __uint_as_float(b);
}

// ---------------- K0: zero accumulators ----------------
__global__ void k0_zero() {
    int t = blockIdx.x * blockDim.x + threadIdx.x;
    int stride = gridDim.x * blockDim.x;
    for (int i = t; i < BMT * NN; i += stride) g_cnt[i] = 0;
    for (int i = t; i < BMT * NC; i += stride) g_DeC[i] = 0.f;
    for (int i = t; i < BMT * NC * FF; i += stride) g_tmpC[i] = 0.f;
}

// ---------------- GEMM (f32x2 packed): out[bm,n,c] = (sum_d x*W + b) * scale
template <int MODE>
__global__ void __launch_bounds__(128) k_gemm(const float* __restrict__ X,
                                              const float* __restrict__ W,
                                              const float* __restrict__ bias,
                                              float scale) {
    constexpr int NCOLS = (MODE == 0) ? PP : FF;
    float* outp = (MODE == 0) ? g_Z : g_Xs;
    __shared__ __align__(16) float sAT[32][72];  // [k][row]
    __shared__ __align__(16) float sWT[32][72];  // [k][col]
    int bm = blockIdx.x;
    int row0 = blockIdx.y * 64;
    int col0 = blockIdx.z * 64;
    int b = bm >> 3, m = bm & 7;
    int tid = threadIdx.x;
    int tr = tid >> 3;  // 0..15 -> 4 rows each
    int tc = tid & 7;   // 0..7  -> 8 cols each
    ull acc2[4][4] = {};
    const float* xbase = X + ((size_t)(b * NN) * 8 + m) * DD;
    for (int k0 = 0; k0 < DD; k0 += 32) {
        for (int t = tid; t < 64 * 32; t += 128) {
            int r = t >> 5, k = t & 31;
            sAT[k][r] = xbase[(size_t)(row0 + r) * 1024 + k0 + k];
            sWT[k][r] = W[(col0 + r) * DD + k0 + k];
        }
        __syncthreads();
#pragma unroll
        for (int k = 0; k < 32; k++) {
            float4 a4 = *(const float4*)&sAT[k][tr * 4];
            ulonglong2 wA = *(const ulonglong2*)&sWT[k][tc * 8];
            ulonglong2 wB = *(const ulonglong2*)&sWT[k][tc * 8 + 4];
            ull a0 = dup2(a4.x), a1 = dup2(a4.y), a2 = dup2(a4.z), a3 = dup2(a4.w);
            fma2(acc2[0][0], a0, wA.x); fma2(acc2[0][1], a0, wA.y);
            fma2(acc2[0][2], a0, wB.x); fma2(acc2[0][3], a0, wB.y);
            fma2(acc2[1][0], a1, wA.x); fma2(acc2[1][1], a1, wA.y);
            fma2(acc2[1][2], a1, wB.x); fma2(acc2[1][3], a1, wB.y);
            fma2(acc2[2][0], a2, wA.x); fma2(acc2[2][1], a2, wA.y);
            fma2(acc2[2][2], a2, wB.x); fma2(acc2[2][3], a2, wB.y);
            fma2(acc2[3][0], a3, wA.x); fma2(acc2[3][1], a3, wA.y);
            fma2(acc2[3][2], a3, wB.x); fma2(acc2[3][3], a3, wB.y);
        }
        __syncthreads();
    }
    float bv[8];
#pragma unroll
    for (int j = 0; j < 8; j++) bv[j] = bias[col0 + tc * 8 + j];
#pragma unroll
    for (int i = 0; i < 4; i++) {
        int n = row0 + tr * 4 + i;
        float f[8];
#pragma unroll
        for (int j2 = 0; j2 < 4; j2++) unpack2(acc2[i][j2], f[2 * j2], f[2 * j2 + 1]);
        float4 o0, o1;
        o0.x = (f[0] + bv[0]) * scale; o0.y = (f[1] + bv[1]) * scale;
        o0.z = (f[2] + bv[2]) * scale; o0.w = (f[3] + bv[3]) * scale;
        o1.x = (f[4] + bv[4]) * scale; o1.y = (f[5] + bv[5]) * scale;
        o1.z = (f[6] + bv[6]) * scale; o1.w = (f[7] + bv[7]) * scale;
        float* op = outp + ((size_t)bm * NN + n) * NCOLS + col0 + tc * 8;
        *(float4*)op = o0;
        *(float4*)(op + 4) = o1;
    }
}

// ---------------- K_cluster_sq: thread-per-row cluster softmax + DeC + sq norm ----
__global__ void __launch_bounds__(256) k_cluster_sq(const float* __restrict__ C) {
    __shared__ float sC[NC * PP];
    __shared__ float sDeC[NC];
    int tid = threadIdx.x;
    for (int t = tid; t < NC * PP; t += 256) sC[t] = C[t];
    if (tid < NC) sDeC[tid] = 0.f;
    __syncthreads();
    int row = blockIdx.x * 256 + tid;
    int bm = row >> 10;
    const float4* z4 = (const float4*)(g_Z + (size_t)row * PP);
    float acc[NC] = {};
    float sq = 0.f;
#pragma unroll
    for (int i = 0; i < 16; i++) {
        float4 v = z4[i];
        sq = fmaf(v.x, v.x, fmaf(v.y, v.y, fmaf(v.z, v.z, fmaf(v.w, v.w, sq))));
#pragma unroll
        for (int c = 0; c < NC; c++) {
            const float* cp = &sC[c * PP + i * 4];
            acc[c] = fmaf(v.x, cp[0], acc[c]);
            acc[c] = fmaf(v.y, cp[1], acc[c]);
            acc[c] = fmaf(v.z, cp[2], acc[c]);
            acc[c] = fmaf(v.w, cp[3], acc[c]);
        }
    }
    g_sq[row] = sq;
    float mx = acc[0];
#pragma unroll
    for (int c = 1; c < NC; c++) mx = fmaxf(mx, acc[c]);
    float p[NC], sum = 0.f;
#pragma unroll
    for (int c = 0; c < NC; c++) {
        p[c] = expf(acc[c] - mx);
        sum += p[c];
    }
    float inv = 1.f / sum;
#pragma unroll
    for (int c = 0; c < NC; c++) {
        p[c] *= inv;
        g_Hc[(size_t)row * NC + c] = p[c];
    }
#pragma unroll
    for (int c = 0; c < NC; c++)
#pragma unroll
        for (int o = 16; o; o >>= 1) p[c] += __shfl_xor_sync(0xffffffffu, p[c], o);
    if ((tid & 31) == 0) {
#pragma unroll
        for (int c = 0; c < NC; c++) atomicAdd(&sDeC[c], p[c]);
    }
    __syncthreads();
    if (tid < NC) atomicAdd(&g_DeC[bm * NC + tid], sDeC[tid]);
}

// ---------------- K2: Gram + streaming top-10 over a j-chunk (split) ----------------
__global__ void __launch_bounds__(128) k_knn() {
    int bm = blockIdx.y >> 2;
    int split = blockIdx.y & 3;
    int n = blockIdx.x * 128 + threadIdx.x;
    const float* Zb = g_Z + (size_t)bm * NN * PP;

    ull zp[32];
    const ull* zr = (const ull*)(Zb + (size_t)n * PP);
#pragma unroll
    for (int i = 0; i < 32; i++) zp[i] = zr[i];
    float sqi = g_sq[bm * NN + n];

    float vals[KK];
    int idxs[KK];
#pragma unroll
    for (int k = 0; k < KK; k++) {
        vals[k] = __int_as_float(0x7f800000);  // +inf
        idxs[k] = 0;
    }

    __shared__ __align__(16) float sZ[32 * 64];
    __shared__ float ssq[32];

    int jbeg = split * JCHUNK;
    for (int j0 = jbeg; j0 < jbeg + JCHUNK; j0 += 32) {
        __syncthreads();
#pragma unroll
        for (int t = threadIdx.x; t < 2048; t += 128)
            sZ[t] = Zb[(size_t)j0 * 64 + t];
        if (threadIdx.x < 32) ssq[threadIdx.x] = g_sq[bm * NN + j0 + threadIdx.x];
        __syncthreads();

#pragma unroll 2
        for (int j = 0; j < 32; j++) {
            const ulonglong2* c2 = (const ulonglong2*)(sZ + j * 64);
            ull a0 = 0ull, a1 = 0ull, a2 = 0ull, a3 = 0ull;
#pragma unroll
            for (int i = 0; i < 8; i++) {
                ulonglong2 v0 = c2[2 * i];
                fma2(a0, zp[4 * i + 0], v0.x);
                fma2(a1, zp[4 * i + 1], v0.y);
                ulonglong2 v1 = c2[2 * i + 1];
                fma2(a2, zp[4 * i + 2], v1.x);
                fma2(a3, zp[4 * i + 3], v1.y);
            }
            a0 = add2(a0, a1);
            a2 = add2(a2, a3);
            a0 = add2(a0, a2);
            float lo, hi;
            unpack2(a0, lo, hi);
            float dot = lo + hi;
            float d2 = sqi + ssq[j] - 2.f * dot;
            if (d2 < vals[KK - 1]) {
                vals[KK - 1] = d2;
                idxs[KK - 1] = j0 + j;
#pragma unroll
                for (int p = KK - 1; p > 0; --p) {
                    bool s = vals[p] < vals[p - 1];  // strict: lower index wins ties
                    float va = vals[p - 1];
                    int ia = idxs[p - 1];
                    vals[p - 1] = s ? vals[p] : va;
                    idxs[p - 1] = s ? idxs[p] : ia;
                    vals[p] = s ? va : vals[p];
                    idxs[p] = s ? ia : idxs[p];
                }
            }
        }
    }

    int base = (((bm * NN + n) << 2) | split) * KK;
#pragma unroll
    for (int k = 0; k < KK; k++) {
        g_pval[base + k] = vals[k];
        g_pidx[base + k] = idxs[k];
    }
}

// ---------------- K2b: merge NSPLIT sorted top-10 lists -> final top-10 ----------------
__global__ void __launch_bounds__(256) k_merge() {
    int row = blockIdx.x * 256 + threadIdx.x;  // 0..BMT*NN-1
    if (row >= BMT * NN) return;
    int bm = row >> 10;
    float vals[KK];
    int idxs[KK];
#pragma unroll
    for (int k = 0; k < KK; k++) {
        vals[k] = __int_as_float(0x7f800000);
        idxs[k] = 0x7fffffff;
    }
    const float* pv = g_pval + (size_t)row * NSPLIT * KK;
    const int* pi = g_pidx + (size_t)row * NSPLIT * KK;
#pragma unroll
    for (int c = 0; c < NSPLIT * KK; c++) {
        float v = pv[c];
        int ix = pi[c];
        bool enter = (v < vals[KK - 1]) || (v == vals[KK - 1] && ix < idxs[KK - 1]);
        if (enter) {
            vals[KK - 1] = v;
            idxs[KK - 1] = ix;
#pragma unroll
            for (int p = KK - 1; p > 0; --p) {
                bool s = (vals[p] < vals[p - 1]) ||
                         (vals[p] == vals[p - 1] && idxs[p] < idxs[p - 1]);
                float va = vals[p - 1];
                int ia = idxs[p - 1];
                vals[p - 1] = s ? vals[p] : va;
                idxs[p - 1] = s ? idxs[p] : ia;
                vals[p] = s ? va : vals[p];
                idxs[p] = s ? ia : idxs[p];
            }
        }
    }
    int base = row * KK;
#pragma unroll
    for (int k = 0; k < KK; k++) {
        g_idx[base + k] = idxs[k];
        atomicAdd(&g_cnt[bm * NN + idxs[k]], 1);
    }
}

// ---------------- K5a: per-bm exclusive scan of counts ----------------
__global__ void __launch_bounds__(1024) k_scan() {
    int bm = blockIdx.x;
    __shared__ int s[NN];
    int t = threadIdx.x;
    int v = g_cnt[bm * NN + t];
    s[t] = v;
    __syncthreads();
    for (int off = 1; off < NN; off <<= 1) {
        int add = (t >= off) ? s[t - off] : 0;
        __syncthreads();
        s[t] += add;
        __syncthreads();
    }
    int excl = s[t] - v;
    g_start[bm * NN + t] = excl;
    g_fill[bm * NN + t] = excl;
}

// ---------------- K5b: fill CSR column lists ----------------
__global__ void k_fill() {
    int gid = blockIdx.x * blockDim.x + threadIdx.x;
    if (gid >= BMT * NN) return;
    int bm = gid >> 10;
    int n = gid & (NN - 1);
#pragma unroll
    for (int k = 0; k < KK; k++) {
        int j = g_idx[gid * KK + k];
        int pos = atomicAdd(&g_fill[bm * NN + j], 1);
        g_list[(size_t)bm * NN * KK + pos] = n;
    }
}

// ---------------- K6: edge aggregation  tmpE[bm,j,:] = De_inv * sum Xs[rows] ----------------
__global__ void __launch_bounds__(128) k_edge() {
    int j = blockIdx.x;
    int bm = blockIdx.y;
    int f = threadIdx.x;
    int cnt = g_cnt[bm * NN + j];
    int st = g_start[bm * NN + j];
    const int* lst = g_list + (size_t)bm * NN * KK + st;
    const float* Xb = g_Xs + (size_t)bm * NN * FF;
    float acc0 = 0.f, acc1 = 0.f, acc2v = 0.f, acc3 = 0.f;
    int i = 0;
    for (; i + 4 <= cnt; i += 4) {
        int n0 = lst[i], n1 = lst[i + 1], n2 = lst[i + 2], n3 = lst[i + 3];
        acc0 += Xb[(size_t)n0 * FF + f];
        acc1 += Xb[(size_t)n1 * FF + f];
        acc2v += Xb[(size_t)n2 * FF + f];
        acc3 += Xb[(size_t)n3 * FF + f];
    }
    for (; i < cnt; i++) acc0 += Xb[(size_t)lst[i] * FF + f];
    float acc = (acc0 + acc1) + (acc2v + acc3);
    float sc = (cnt > 0) ? (1.f / (float)cnt) : 0.f;
    g_tmpE[((size_t)bm * NN + j) * FF + f] = acc * sc;
}

// ---------------- K6b: cluster aggregation ----------------
__global__ void __launch_bounds__(128) k_cagg() {
    int bm = blockIdx.y;
    int base = blockIdx.x * 128;
    int f = threadIdx.x;
    __shared__ float sH[128 * NC];
    for (int t = f; t < 128 * NC; t += 128)
        sH[t] = g_Hc[((size_t)bm * NN + base) * NC + t];
    __syncthreads();
    float acc[NC] = {};
#pragma unroll 4
    for (int nn = 0; nn < 128; nn++) {
        float x = g_Xs[((size_t)bm * NN + base + nn) * FF + f];
#pragma unroll
        for (int c = 0; c < NC; c++) acc[c] = fmaf(sH[nn * NC + c], x, acc[c]);
    }
#pragma unroll
    for (int c = 0; c < NC; c++)
        atomicAdd(&g_tmpC[((size_t)bm * NC + c) * FF + f], acc[c]);
}

// ---------------- K7: final gather + cluster term + elu + output layout ----------------
__global__ void __launch_bounds__(128) k_final(float* __restrict__ out) {
    int bm = blockIdx.y;
    int base = blockIdx.x * 32;
    int f = threadIdx.x;
    __shared__ float sC[NC * FF];
    __shared__ float sH[32 * NC];
    __shared__ int sI[32 * KK];
    __shared__ float sDi[NC];
    if (f < NC) sDi[f] = 1.f / g_DeC[bm * NC + f];
    __syncthreads();
#pragma unroll
    for (int c = 0; c < NC; c++)
        sC[c * FF + f] = g_tmpC[((size_t)bm * NC + c) * FF + f] * sDi[c];
    for (int t = f; t < 32 * NC; t += 128) {
        sH[t] = g_Hc[((size_t)bm * NN + base) * NC + t];
        sI[t] = g_idx[((size_t)bm * NN + base) * KK + t];
    }
    __syncthreads();
    int b = bm >> 3, m = bm & 7;
    const float* Eb = g_tmpE + (size_t)bm * NN * FF;
#pragma unroll 2
    for (int r = 0; r < 32; r++) {
        float acc = 0.f;
#pragma unroll
        for (int k = 0; k < KK; k++) {
            int j = sI[r * KK + k];
            acc += Eb[(size_t)j * FF + f];
        }
#pragma unroll
        for (int c = 0; c < NC; c++)
            acc = fmaf(sH[r * NC + c], sC[c * FF + f], acc);
        float v = INV_SQRT11 * acc;
        v = (v > 0.f) ? v : expm1f(v);
        out[(((size_t)b * NN + base + r) * 8 + m) * FF + f] = v;
    }
}

// ---------------- launch ----------------
extern "C" void kernel_launch(void* const* d_in, const int* in_sizes, int n_in,
                              void* d_out, int out_size) {
    const float* x   = (const float*)d_in[0];  // [4,1024,8,128]
    const float* Wp  = (const float*)d_in[1];  // [64,128]
    const float* Wpb = (const float*)d_in[2];  // [64]
    const float* C   = (const float*)d_in[3];  // [10,64]
    const float* Tw  = (const float*)d_in[4];  // [128,128]
    const float* Tb  = (const float*)d_in[5];  // [128]
    float* out = (float*)d_out;

    k0_zero<<<64, 256>>>();                                                  // 1
    k_gemm<0><<<dim3(BMT, NN / 64, 1), 128>>>(x, Wp, Wpb, 1.0f);             // 2: Z
    k_cluster_sq<<<(BMT * NN) / 256, 256>>>(C);                              // 3
    k_knn<<<dim3(NN / 128, BMT * NSPLIT), 128>>>();                          // 4: Gram + partial top-10
    k_merge<<<(BMT * NN) / 256, 256>>>();                                    // 5: merge + counts
    k_gemm<1><<<dim3(BMT, NN / 64, 2), 128>>>(x, Tw, Tb, INV_SQRT11);        // 6: Xs
    k_scan<<<BMT, 1024>>>();                                                 // 7
    k_fill<<<(BMT * NN + 255) / 256, 256>>>();                               // 8
    k_edge<<<dim3(NN, BMT), 128>>>();                                        // 9
    k_cagg<<<dim3(NN / 128, BMT), 128>>>();                                  // 10
    k_final<<<dim3(NN / 32, BMT), 128>>>(out);                               // 11
}